// round 2
// baseline (speedup 1.0000x reference)
#include <cuda_runtime.h>
#include <math.h>

#define NNODES 100000
#define NEDGES 640000
#define DD 128
#define WS_STRIDE 130              // float2 stride, padded to avoid k-dim bank conflicts
#define ROWTILES 4                 // 4 x 128-row tiles per block (amortize W smem prologue)

// Scratch (allocation-free rule: __device__ globals)
__device__ float g_conv[NNODES * DD];
__device__ float g_agg[NNODES * DD];
__device__ int   g_sdeg[NNODES];
__device__ int   g_rdeg[NNODES];
__device__ float g_gvec[DD];
__device__ float g_an[DD];

// ---------------------------------------------------------------- zeroing
__global__ void k_zero() {
    int i = blockIdx.x * blockDim.x + threadIdx.x;
    const int NA4 = NNODES * DD / 4;
    if (i < NA4) ((float4*)g_agg)[i] = make_float4(0.f, 0.f, 0.f, 0.f);
    if (i < NNODES) { g_sdeg[i] = 0; g_rdeg[i] = 0; }
    if (i < DD) g_an[i] = 0.f;
}

// ---------------------------------------------------------------- degrees
__global__ void k_deg(const int* __restrict__ snd, const int* __restrict__ rcv) {
    int e = blockIdx.x * blockDim.x + threadIdx.x;
    if (e < NEDGES) {
        atomicAdd(&g_sdeg[snd[e]], 1);
        atomicAdd(&g_rdeg[rcv[e]], 1);
    }
}

// ---------------------------------------------------------------- tf32 helpers
__device__ __forceinline__ void tf32split(float f, unsigned& hi, unsigned& lo) {
    unsigned h;
    asm("cvt.rna.tf32.f32 %0, %1;" : "=r"(h) : "f"(f));
    hi = h;
    lo = __float_as_uint(f - __uint_as_float(h));   // residual; implicit truncation to tf32 is fine
}

#define MMA_TF32(C, A0, A1, A2, A3, B0, B1)                                    \
    asm volatile("mma.sync.aligned.m16n8k8.row.col.f32.tf32.tf32.f32 "          \
                 "{%0,%1,%2,%3}, {%4,%5,%6,%7}, {%8,%9}, {%0,%1,%2,%3};"        \
                 : "+f"((C)[0]), "+f"((C)[1]), "+f"((C)[2]), "+f"((C)[3])       \
                 : "r"(A0), "r"(A1), "r"(A2), "r"(A3), "r"(B0), "r"(B1))

// ---------------------------------------------------------------- tensor-core GEMM
// grid.y==0: h1 = nodes@W1 + b1                      -> out_h
// grid.y==1: conv = (nodes@W2 + b2) * rsqrt(sdeg)    -> g_conv
// Block: 256 threads (8 warps). Per block: ROWTILES x 128 rows, all 128 cols.
// Per warp: 16 rows x 128 cols per tile. 3xTF32 split => ~fp32 accuracy.
extern __shared__ float2 Ws[];   // [128][WS_STRIDE] (hi, lo) of W
__global__ __launch_bounds__(256, 1) void k_gemm(
    const float* __restrict__ A,
    const float* __restrict__ W1, const float* __restrict__ b1,
    const float* __restrict__ W2, const float* __restrict__ b2,
    float* __restrict__ out_h)
{
    const int which = blockIdx.y;
    const float* W    = which ? W2 : W1;
    const float* bias = which ? b2 : b1;
    float* dst        = which ? g_conv : out_h;

    const int tid  = threadIdx.x;
    const int warp = tid >> 5;
    const int lane = tid & 31;
    const int g  = lane >> 2;        // groupID 0..7
    const int tq = lane & 3;         // quad 0..3

    // ---- prologue: W (hi,lo) into padded shared, once per block
    for (int idx = tid; idx < DD * DD; idx += 256) {
        int k = idx >> 7, n = idx & 127;
        unsigned hi, lo;
        tf32split(W[idx], hi, lo);
        Ws[k * WS_STRIDE + n] = make_float2(__uint_as_float(hi), __uint_as_float(lo));
    }
    __syncthreads();

    #pragma unroll 1
    for (int t = 0; t < ROWTILES; t++) {
        const int rowBase = (blockIdx.x * ROWTILES + t) * 128;
        if (rowBase >= NNODES) break;

        const int r0 = rowBase + warp * 16 + g;
        const int r1 = r0 + 8;
        const int rl0 = r0 < NNODES ? r0 : NNODES - 1;   // clamp loads, guard stores
        const int rl1 = r1 < NNODES ? r1 : NNODES - 1;
        const float* Ar0 = A + (long)rl0 * DD;
        const float* Ar1 = A + (long)rl1 * DD;

        float c[16][4];
        #pragma unroll
        for (int nt = 0; nt < 16; nt++)
            { c[nt][0] = 0.f; c[nt][1] = 0.f; c[nt][2] = 0.f; c[nt][3] = 0.f; }

        #pragma unroll 4
        for (int kc = 0; kc < DD; kc += 8) {
            unsigned ah0, al0, ah1, al1, ah2, al2, ah3, al3;
            tf32split(Ar0[kc + tq],     ah0, al0);
            tf32split(Ar1[kc + tq],     ah1, al1);
            tf32split(Ar0[kc + tq + 4], ah2, al2);
            tf32split(Ar1[kc + tq + 4], ah3, al3);
            const float2* wrow0 = &Ws[(kc + tq) * WS_STRIDE + g];
            const float2* wrow1 = &Ws[(kc + tq + 4) * WS_STRIDE + g];
            #pragma unroll
            for (int nt = 0; nt < 16; nt++) {
                float2 w0 = wrow0[nt * 8];
                float2 w1 = wrow1[nt * 8];
                unsigned bh0 = __float_as_uint(w0.x), bl0 = __float_as_uint(w0.y);
                unsigned bh1 = __float_as_uint(w1.x), bl1 = __float_as_uint(w1.y);
                MMA_TF32(c[nt], ah0, ah1, ah2, ah3, bh0, bh1);   // hi*hi
                MMA_TF32(c[nt], ah0, ah1, ah2, ah3, bl0, bl1);   // hi*lo
                MMA_TF32(c[nt], al0, al1, al2, al3, bh0, bh1);   // lo*hi
            }
        }

        // ---- epilogue
        float rs0 = 1.f, rs1 = 1.f;
        if (which) {
            rs0 = rsqrtf(fmaxf((float)g_sdeg[rl0], 1.0f));
            rs1 = rsqrtf(fmaxf((float)g_sdeg[rl1], 1.0f));
        }
        #pragma unroll
        for (int nt = 0; nt < 16; nt++) {
            int cbase = nt * 8 + 2 * tq;
            float2 bb = *(const float2*)(bias + cbase);
            float2 p0 = make_float2((c[nt][0] + bb.x) * rs0, (c[nt][1] + bb.y) * rs0);
            float2 p1 = make_float2((c[nt][2] + bb.x) * rs1, (c[nt][3] + bb.y) * rs1);
            if (r0 < NNODES) *(float2*)(dst + (long)r0 * DD + cbase) = p0;
            if (r1 < NNODES) *(float2*)(dst + (long)r1 * DD + cbase) = p1;
        }
    }
}

// ---------------------------------------------------------------- gvec = globals@W3 + b3 (parallel)
__global__ void k_gvec(const float* __restrict__ gl, const float* __restrict__ W3,
                       const float* __restrict__ b3) {
    __shared__ float red[DD];
    int c = blockIdx.x, t = threadIdx.x;          // 128 blocks x 128 threads
    red[t] = gl[t] * W3[t * DD + c];
    __syncthreads();
    if (t < 64) red[t] += red[t + 64];
    __syncthreads();
    if (t < 32) {
        float v = red[t] + red[t + 32];
        #pragma unroll
        for (int o = 16; o > 0; o >>= 1) v += __shfl_down_sync(0xffffffff, v, o);
        if (t == 0) g_gvec[c] = v + b3[c];
    }
}

// ---------------------------------------------------------------- edge scatter-add
__global__ __launch_bounds__(256) void k_agg(const int* __restrict__ snd,
                                             const int* __restrict__ rcv) {
    int warp = (blockIdx.x * 256 + threadIdx.x) >> 5;
    int lane = threadIdx.x & 31;
    if (warp < NEDGES) {
        int s = __ldg(&snd[warp]);
        int r = __ldg(&rcv[warp]);
        float4 v = ((const float4*)g_conv)[(long)s * 32 + lane];
        float* addr = &g_agg[(long)r * DD + lane * 4];
        asm volatile("red.global.add.v4.f32 [%0], {%1,%2,%3,%4};"
                     :: "l"(addr), "f"(v.x), "f"(v.y), "f"(v.z), "f"(v.w)
                     : "memory");
    }
}

// ---------------------------------------------------------------- fused epilogue + column sums
__global__ __launch_bounds__(256) void k_final(const float* __restrict__ nodes,
                                               float* __restrict__ out) {
    __shared__ float4 sred[256];
    const int tid  = threadIdx.x;
    const int lane = tid & 31;
    const int ty   = tid >> 5;
    const int rowBase = blockIdx.x * 64;
    float4 gv = ((const float4*)g_gvec)[lane];
    float4 sum = make_float4(0.f, 0.f, 0.f, 0.f);

    #pragma unroll
    for (int i = 0; i < 8; i++) {
        int r = rowBase + ty * 8 + i;
        if (r < NNODES) {
            long off = (long)r * 32 + lane;
            float4 h  = ((float4*)out)[off];
            float4 a  = ((const float4*)g_agg)[off];
            float4 nd = ((const float4*)nodes)[off];
            float rs = rsqrtf(fmaxf((float)g_rdeg[r], 1.0f));
            float4 o;
            o.x = fmaxf(h.x + a.x * rs + gv.x, 0.f) + nd.x;
            o.y = fmaxf(h.y + a.y * rs + gv.y, 0.f) + nd.y;
            o.z = fmaxf(h.z + a.z * rs + gv.z, 0.f) + nd.z;
            o.w = fmaxf(h.w + a.w * rs + gv.w, 0.f) + nd.w;
            ((float4*)out)[off] = o;
            sum.x += o.x; sum.y += o.y; sum.z += o.z; sum.w += o.w;
        }
    }
    sred[tid] = sum;
    __syncthreads();
    if (ty == 0) {
        float4 s = sred[lane];
        #pragma unroll
        for (int j = 1; j < 8; j++) {
            float4 t = sred[j * 32 + lane];
            s.x += t.x; s.y += t.y; s.z += t.z; s.w += t.w;
        }
        float* addr = &g_an[lane * 4];
        asm volatile("red.global.add.v4.f32 [%0], {%1,%2,%3,%4};"
                     :: "l"(addr), "f"(s.x), "f"(s.y), "f"(s.z), "f"(s.w)
                     : "memory");
    }
}

// ---------------------------------------------------------------- global update (parallel)
__global__ void k_global(const float* __restrict__ gl, const float* __restrict__ Wg,
                         const float* __restrict__ bg, float* __restrict__ outg) {
    __shared__ float red[2 * DD];
    int c = blockIdx.x, t = threadIdx.x;          // 128 blocks x 256 threads
    float x = (t < DD) ? g_an[t] : gl[t - DD];
    red[t] = x * Wg[t * DD + c];
    __syncthreads();
    if (t < 128) red[t] += red[t + 128];
    __syncthreads();
    if (t < 64) red[t] += red[t + 64];
    __syncthreads();
    if (t < 32) {
        float v = red[t] + red[t + 32];
        #pragma unroll
        for (int o = 16; o > 0; o >>= 1) v += __shfl_down_sync(0xffffffff, v, o);
        if (t == 0) outg[c] = gl[c] + fmaxf(v + bg[c], 0.f);
    }
}

// ---------------------------------------------------------------- launch
extern "C" void kernel_launch(void* const* d_in, const int* in_sizes, int n_in,
                              void* d_out, int out_size) {
    const float* nodes    = (const float*)d_in[0];
    const float* globals_ = (const float*)d_in[1];
    const int*   senders   = (const int*)d_in[2];
    const int*   receivers = (const int*)d_in[3];
    const float* W1w = (const float*)d_in[4];
    const float* W1b = (const float*)d_in[5];
    const float* W2w = (const float*)d_in[6];
    const float* W2b = (const float*)d_in[7];
    const float* W3w = (const float*)d_in[8];
    const float* W3b = (const float*)d_in[9];
    const float* Wgw = (const float*)d_in[10];
    const float* Wgb = (const float*)d_in[11];
    float* out = (float*)d_out;

    const int smem = DD * WS_STRIDE * sizeof(float2);   // 133,120 B
    cudaFuncSetAttribute(k_gemm, cudaFuncAttributeMaxDynamicSharedMemorySize, smem);

    k_zero<<<12500, 256>>>();
    k_deg<<<(NEDGES + 255) / 256, 256>>>(senders, receivers);
    dim3 gg((NNODES + ROWTILES * 128 - 1) / (ROWTILES * 128), 2);
    k_gemm<<<gg, 256, smem>>>(nodes, W1w, W1b, W2w, W2b, out);
    k_gvec<<<DD, DD>>>(globals_, W3w, W3b);
    k_agg<<<(NEDGES + 7) / 8, 256>>>(senders, receivers);
    k_final<<<(NNODES + 63) / 64, 256>>>(nodes, out);
    k_global<<<DD, 2 * DD>>>(globals_, Wgw, Wgb, out + (long)NNODES * DD);
}

// round 5
// speedup vs baseline: 1.3019x; 1.3019x over previous
#include <cuda_runtime.h>
#include <cuda_fp16.h>
#include <math.h>
#include <stdint.h>

#define NNODES 100000
#define NEDGES 640000
#define DD 128

// Scratch (__device__ globals: allocation-free rule)
__device__ __half g_conv_h[NNODES * DD];   // conv = (nodes@W2+b2)*rsqrt(sdeg), fp16
__device__ float  g_agg[NNODES * DD];
__device__ int    g_sdeg[NNODES];
__device__ int    g_rdeg[NNODES];
__device__ float  g_gvec[DD];
__device__ float  g_an[DD];

// packed fp32x2 FMA (Blackwell FFMA2; only reachable via explicit PTX)
#define FMA_F32X2(acc, a, b) \
    asm("fma.rn.f32x2 %0, %1, %2, %0;" : "+l"(acc) : "l"(a), "l"(b))

__device__ __forceinline__ unsigned long long dup2(float f) {
    unsigned u = __float_as_uint(f);
    return (unsigned long long)u | ((unsigned long long)u << 32);
}
__device__ __forceinline__ float2 unpk(unsigned long long v) {
    return make_float2(__uint_as_float((unsigned)v), __uint_as_float((unsigned)(v >> 32)));
}

// ---------------------------------------------------------------- zero + gvec fused
__global__ void k_zero(const float* __restrict__ gl, const float* __restrict__ W3,
                       const float* __restrict__ b3) {
    int i = blockIdx.x * blockDim.x + threadIdx.x;
    const int NA4 = NNODES * DD / 4;
    if (i < NA4) ((float4*)g_agg)[i] = make_float4(0.f, 0.f, 0.f, 0.f);
    if (i < NNODES) { g_sdeg[i] = 0; g_rdeg[i] = 0; }
    if (i < DD) g_an[i] = 0.f;
    if (blockIdx.x < DD) {           // blocks 0..127: g_gvec[c] = globals@W3[:,c] + b3[c]
        __shared__ float red[DD];
        int c = blockIdx.x, t = threadIdx.x;
        if (t < DD) red[t] = gl[t] * W3[t * DD + c];
        __syncthreads();
        if (t < 64) red[t] += red[t + 64];
        __syncthreads();
        if (t < 32) {
            float v = red[t] + red[t + 32];
            #pragma unroll
            for (int o = 16; o > 0; o >>= 1) v += __shfl_down_sync(0xffffffff, v, o);
            if (t == 0) g_gvec[c] = v + b3[c];
        }
    }
}

// ---------------------------------------------------------------- degrees
__global__ void k_deg(const int* __restrict__ snd, const int* __restrict__ rcv) {
    int e = blockIdx.x * blockDim.x + threadIdx.x;
    if (e < NEDGES) {
        atomicAdd(&g_sdeg[snd[e]], 1);
        atomicAdd(&g_rdeg[rcv[e]], 1);
    }
}

// ---------------------------------------------------------------- f32x2 GEMM
// grid.y==0: h1 = nodes@W1 + b1                    -> out_h (fp32)
// grid.y==1: conv = (nodes@W2+b2)*rsqrt(sdeg)      -> g_conv_h (fp16)
// Block 256 thr, tile 64 rows x 128 cols. Warp = 8 rows x 128 cols.
// A tile in smem pre-duplicated as (a,a) u64 pairs; W read as ulonglong2 (L1-hot).
extern __shared__ unsigned long long As2[];   // [64 rows][128 k] 8B pairs = 64KB
__global__ __launch_bounds__(256) void k_gemm(
    const float* __restrict__ A,
    const float* __restrict__ W1, const float* __restrict__ b1,
    const float* __restrict__ W2, const float* __restrict__ b2,
    float* __restrict__ out_h)
{
    const int which = blockIdx.y;
    const float* W    = which ? W2 : W1;
    const float* bias = which ? b2 : b1;
    const int rowBase = blockIdx.x * 64;
    const int tid = threadIdx.x;
    const int maxr = NNODES - rowBase;

    // Load + duplicate A tile [64 x 128]
    const float4* A4 = (const float4*)(A + (long)rowBase * DD);
    #pragma unroll
    for (int i = 0; i < 8; i++) {
        int idx4 = tid + i * 256;                // 2048 float4 slots; row = idx4>>5
        int row = idx4 >> 5, col4 = (idx4 & 31) << 2;
        float4 v = make_float4(0.f, 0.f, 0.f, 0.f);
        if (row < maxr) v = A4[idx4];
        unsigned long long* d = &As2[row * DD + col4];
        d[0] = dup2(v.x); d[1] = dup2(v.y); d[2] = dup2(v.z); d[3] = dup2(v.w);
    }
    __syncthreads();

    const int lane = tid & 31;                   // cols lane*4..+3 (two f32x2 pairs)
    const int ty   = tid >> 5;                   // rows ty*8..+7
    unsigned long long acc[8][2];
    #pragma unroll
    for (int i = 0; i < 8; i++) { acc[i][0] = 0ull; acc[i][1] = 0ull; }

    const unsigned long long* Asrow = &As2[ty * 8 * DD];
    #pragma unroll 8
    for (int k = 0; k < DD; k++) {
        ulonglong2 wp = *(const ulonglong2*)(W + (long)k * DD + lane * 4); // (w0,w1),(w2,w3)
        #pragma unroll
        for (int i = 0; i < 8; i++) {
            unsigned long long ap = Asrow[i * DD + k];   // broadcast LDS.64
            FMA_F32X2(acc[i][0], ap, wp.x);
            FMA_F32X2(acc[i][1], ap, wp.y);
        }
    }

    float4 bv = ((const float4*)bias)[lane];
    #pragma unroll
    for (int i = 0; i < 8; i++) {
        int r = ty * 8 + i;
        if (r < maxr) {
            int gr = rowBase + r;
            float2 p0 = unpk(acc[i][0]);
            float2 p1 = unpk(acc[i][1]);
            float4 o = make_float4(p0.x + bv.x, p0.y + bv.y, p1.x + bv.z, p1.y + bv.w);
            if (which) {
                float rs = rsqrtf(fmaxf((float)g_sdeg[gr], 1.0f));
                __half2 h01 = __floats2half2_rn(o.x * rs, o.y * rs);
                __half2 h23 = __floats2half2_rn(o.z * rs, o.w * rs);
                uint2 pk;
                pk.x = *(unsigned*)&h01; pk.y = *(unsigned*)&h23;
                *(uint2*)&g_conv_h[(long)gr * DD + lane * 4] = pk;
            } else {
                ((float4*)out_h)[(long)gr * 32 + lane] = o;
            }
        }
    }
}

// ---------------------------------------------------------------- edge scatter-add
// One warp per edge; lane covers 4 cols; fp16 gather (8B) + v4.f32 reduction.
__global__ __launch_bounds__(256) void k_agg(const int* __restrict__ snd,
                                             const int* __restrict__ rcv) {
    int warp = (blockIdx.x * 256 + threadIdx.x) >> 5;
    int lane = threadIdx.x & 31;
    if (warp < NEDGES) {
        int s = __ldg(&snd[warp]);
        int r = __ldg(&rcv[warp]);
        uint2 raw = *(const uint2*)&g_conv_h[(long)s * DD + lane * 4];
        float2 f01 = __half22float2(*(__half2*)&raw.x);
        float2 f23 = __half22float2(*(__half2*)&raw.y);
        float* addr = &g_agg[(long)r * DD + lane * 4];
        asm volatile("red.global.add.v4.f32 [%0], {%1,%2,%3,%4};"
                     :: "l"(addr), "f"(f01.x), "f"(f01.y), "f"(f23.x), "f"(f23.y)
                     : "memory");
    }
}

// ---------------------------------------------------------------- fused epilogue + column sums
__global__ __launch_bounds__(256) void k_final(const float* __restrict__ nodes,
                                               float* __restrict__ out) {
    __shared__ float4 sred[256];
    const int tid  = threadIdx.x;
    const int lane = tid & 31;
    const int ty   = tid >> 5;
    const int rowBase = blockIdx.x * 64;
    float4 gv = ((const float4*)g_gvec)[lane];
    float4 sum = make_float4(0.f, 0.f, 0.f, 0.f);

    #pragma unroll
    for (int i = 0; i < 8; i++) {
        int r = rowBase + ty * 8 + i;
        if (r < NNODES) {
            long off = (long)r * 32 + lane;
            float4 h  = ((float4*)out)[off];
            float4 a  = ((const float4*)g_agg)[off];
            float4 nd = ((const float4*)nodes)[off];
            float rs = rsqrtf(fmaxf((float)g_rdeg[r], 1.0f));
            float4 o;
            o.x = fmaxf(h.x + a.x * rs + gv.x, 0.f) + nd.x;
            o.y = fmaxf(h.y + a.y * rs + gv.y, 0.f) + nd.y;
            o.z = fmaxf(h.z + a.z * rs + gv.z, 0.f) + nd.z;
            o.w = fmaxf(h.w + a.w * rs + gv.w, 0.f) + nd.w;
            ((float4*)out)[off] = o;
            sum.x += o.x; sum.y += o.y; sum.z += o.z; sum.w += o.w;
        }
    }
    sred[tid] = sum;
    __syncthreads();
    if (ty == 0) {
        float4 s = sred[lane];
        #pragma unroll
        for (int j = 1; j < 8; j++) {
            float4 t = sred[j * 32 + lane];
            s.x += t.x; s.y += t.y; s.z += t.z; s.w += t.w;
        }
        float* addr = &g_an[lane * 4];
        asm volatile("red.global.add.v4.f32 [%0], {%1,%2,%3,%4};"
                     :: "l"(addr), "f"(s.x), "f"(s.y), "f"(s.z), "f"(s.w)
                     : "memory");
    }
}

// ---------------------------------------------------------------- global update
__global__ void k_global(const float* __restrict__ gl, const float* __restrict__ Wg,
                         const float* __restrict__ bg, float* __restrict__ outg) {
    __shared__ float red[2 * DD];
    int c = blockIdx.x, t = threadIdx.x;          // 128 blocks x 256 threads
    float x = (t < DD) ? g_an[t] : gl[t - DD];
    red[t] = x * Wg[t * DD + c];
    __syncthreads();
    if (t < 128) red[t] += red[t + 128];
    __syncthreads();
    if (t < 64) red[t] += red[t + 64];
    __syncthreads();
    if (t < 32) {
        float v = red[t] + red[t + 32];
        #pragma unroll
        for (int o = 16; o > 0; o >>= 1) v += __shfl_down_sync(0xffffffff, v, o);
        if (t == 0) outg[c] = gl[c] + fmaxf(v + bg[c], 0.f);
    }
}

// ---------------------------------------------------------------- launch
extern "C" void kernel_launch(void* const* d_in, const int* in_sizes, int n_in,
                              void* d_out, int out_size) {
    const float* nodes    = (const float*)d_in[0];
    const float* globals_ = (const float*)d_in[1];
    const int*   senders   = (const int*)d_in[2];
    const int*   receivers = (const int*)d_in[3];
    const float* W1w = (const float*)d_in[4];
    const float* W1b = (const float*)d_in[5];
    const float* W2w = (const float*)d_in[6];
    const float* W2b = (const float*)d_in[7];
    const float* W3w = (const float*)d_in[8];
    const float* W3b = (const float*)d_in[9];
    const float* Wgw = (const float*)d_in[10];
    const float* Wgb = (const float*)d_in[11];
    float* out = (float*)d_out;

    const int smem = 64 * DD * 8;    // 65536 B
    cudaFuncSetAttribute(k_gemm, cudaFuncAttributeMaxDynamicSharedMemorySize, smem);

    k_zero<<<12500, 256>>>(globals_, W3w, W3b);
    k_deg<<<(NEDGES + 255) / 256, 256>>>(senders, receivers);
    dim3 gg((NNODES + 63) / 64, 2);
    k_gemm<<<gg, 256, smem>>>(nodes, W1w, W1b, W2w, W2b, out);
    k_agg<<<(NEDGES + 7) / 8, 256>>>(senders, receivers);
    k_final<<<(NNODES + 63) / 64, 256>>>(nodes, out);
    k_global<<<DD, 2 * DD>>>(globals_, Wgw, Wgb, out + (long)NNODES * DD);
}

// round 6
// speedup vs baseline: 1.4214x; 1.0919x over previous
#include <cuda_runtime.h>
#include <cuda_fp16.h>
#include <math.h>
#include <stdint.h>

#define NNODES 100000
#define NEDGES 640000
#define DD 128
#define SCAN_BLK 98            // ceil(100000/1024)

// Scratch (__device__ globals: allocation-free rule)
__device__ __half g_conv_h[NNODES * DD];   // conv = (nodes@W2+b2)*rsqrt(sdeg), fp16
__device__ int    g_sdeg[NNODES];
__device__ int    g_rdeg[NNODES];
__device__ int    g_scan[NNODES];          // per-block inclusive scan of rdeg
__device__ int    g_bsum[SCAN_BLK];
__device__ int    g_boff[SCAN_BLK];
__device__ int    g_offs[NNODES];          // exclusive prefix (CSR row starts)
__device__ int    g_cur[NNODES];           // scatter cursors
__device__ int    g_csr[NEDGES];           // sender index per in-edge, grouped by receiver
__device__ float  g_gvec[DD];
__device__ float  g_an[DD];

// packed fp32x2 FMA
#define FMA_F32X2(acc, a, b) \
    asm("fma.rn.f32x2 %0, %1, %2, %0;" : "+l"(acc) : "l"(a), "l"(b))

__device__ __forceinline__ unsigned long long dup2(float f) {
    unsigned u = __float_as_uint(f);
    return (unsigned long long)u | ((unsigned long long)u << 32);
}
__device__ __forceinline__ float2 unpk(unsigned long long v) {
    return make_float2(__uint_as_float((unsigned)v), __uint_as_float((unsigned)(v >> 32)));
}

// ---------------------------------------------------------------- zero + gvec fused
__global__ void k_zero(const float* __restrict__ gl, const float* __restrict__ W3,
                       const float* __restrict__ b3) {
    int i = blockIdx.x * blockDim.x + threadIdx.x;     // 391*256
    if (i < NNODES) { g_sdeg[i] = 0; g_rdeg[i] = 0; }
    if (i < DD) g_an[i] = 0.f;
    if (blockIdx.x < DD) {           // blocks 0..127: g_gvec[c] = globals@W3[:,c] + b3[c]
        __shared__ float red[DD];
        int c = blockIdx.x, t = threadIdx.x;
        if (t < DD) red[t] = gl[t] * W3[t * DD + c];
        __syncthreads();
        if (t < 64) red[t] += red[t + 64];
        __syncthreads();
        if (t < 32) {
            float v = red[t] + red[t + 32];
            #pragma unroll
            for (int o = 16; o > 0; o >>= 1) v += __shfl_down_sync(0xffffffff, v, o);
            if (t == 0) g_gvec[c] = v + b3[c];
        }
    }
}

// ---------------------------------------------------------------- degrees
__global__ void k_deg(const int* __restrict__ snd, const int* __restrict__ rcv) {
    int e = blockIdx.x * blockDim.x + threadIdx.x;
    if (e < NEDGES) {
        atomicAdd(&g_sdeg[snd[e]], 1);
        atomicAdd(&g_rdeg[rcv[e]], 1);
    }
}

// ---------------------------------------------------------------- prefix scan (3 stages)
__global__ __launch_bounds__(1024) void k_scanA() {       // 98 blocks x 1024
    __shared__ int sh[1024];
    int i = blockIdx.x * 1024 + threadIdx.x;
    int v = (i < NNODES) ? g_rdeg[i] : 0;
    sh[threadIdx.x] = v;
    __syncthreads();
    #pragma unroll
    for (int o = 1; o < 1024; o <<= 1) {
        int t = (threadIdx.x >= o) ? sh[threadIdx.x - o] : 0;
        __syncthreads();
        sh[threadIdx.x] += t;
        __syncthreads();
    }
    if (i < NNODES) g_scan[i] = sh[threadIdx.x];
    if (threadIdx.x == 1023) g_bsum[blockIdx.x] = sh[1023];
}
__global__ void k_scanB() {                               // 1 block x 128
    __shared__ int sh[128];
    int t = threadIdx.x;
    int v = (t < SCAN_BLK) ? g_bsum[t] : 0;
    sh[t] = v;
    __syncthreads();
    #pragma unroll
    for (int o = 1; o < 128; o <<= 1) {
        int u = (t >= o) ? sh[t - o] : 0;
        __syncthreads();
        sh[t] += u;
        __syncthreads();
    }
    if (t < SCAN_BLK) g_boff[t] = sh[t] - v;              // exclusive
}
__global__ void k_scanC() {                               // 391 blocks x 256
    int i = blockIdx.x * blockDim.x + threadIdx.x;
    if (i < NNODES) {
        int off = g_scan[i] - g_rdeg[i] + g_boff[i >> 10];
        g_offs[i] = off;
        g_cur[i]  = off;
    }
}

// ---------------------------------------------------------------- CSR scatter (sender ids)
__global__ void k_scatter(const int* __restrict__ snd, const int* __restrict__ rcv) {
    int e = blockIdx.x * blockDim.x + threadIdx.x;
    if (e < NEDGES) {
        int r = rcv[e];
        int pos = atomicAdd(&g_cur[r], 1);
        g_csr[pos] = snd[e];
    }
}

// ---------------------------------------------------------------- f32x2 GEMM (unchanged)
extern __shared__ unsigned long long As2[];   // [64 rows][128 k] 8B pairs = 64KB
__global__ __launch_bounds__(256) void k_gemm(
    const float* __restrict__ A,
    const float* __restrict__ W1, const float* __restrict__ b1,
    const float* __restrict__ W2, const float* __restrict__ b2,
    float* __restrict__ out_h)
{
    const int which = blockIdx.y;
    const float* W    = which ? W2 : W1;
    const float* bias = which ? b2 : b1;
    const int rowBase = blockIdx.x * 64;
    const int tid = threadIdx.x;
    const int maxr = NNODES - rowBase;

    const float4* A4 = (const float4*)(A + (long)rowBase * DD);
    #pragma unroll
    for (int i = 0; i < 8; i++) {
        int idx4 = tid + i * 256;
        int row = idx4 >> 5, col4 = (idx4 & 31) << 2;
        float4 v = make_float4(0.f, 0.f, 0.f, 0.f);
        if (row < maxr) v = A4[idx4];
        unsigned long long* d = &As2[row * DD + col4];
        d[0] = dup2(v.x); d[1] = dup2(v.y); d[2] = dup2(v.z); d[3] = dup2(v.w);
    }
    __syncthreads();

    const int lane = tid & 31;
    const int ty   = tid >> 5;
    unsigned long long acc[8][2];
    #pragma unroll
    for (int i = 0; i < 8; i++) { acc[i][0] = 0ull; acc[i][1] = 0ull; }

    const unsigned long long* Asrow = &As2[ty * 8 * DD];
    #pragma unroll 8
    for (int k = 0; k < DD; k++) {
        ulonglong2 wp = *(const ulonglong2*)(W + (long)k * DD + lane * 4);
        #pragma unroll
        for (int i = 0; i < 8; i++) {
            unsigned long long ap = Asrow[i * DD + k];
            FMA_F32X2(acc[i][0], ap, wp.x);
            FMA_F32X2(acc[i][1], ap, wp.y);
        }
    }

    float4 bv = ((const float4*)bias)[lane];
    #pragma unroll
    for (int i = 0; i < 8; i++) {
        int r = ty * 8 + i;
        if (r < maxr) {
            int gr = rowBase + r;
            float2 p0 = unpk(acc[i][0]);
            float2 p1 = unpk(acc[i][1]);
            float4 o = make_float4(p0.x + bv.x, p0.y + bv.y, p1.x + bv.z, p1.y + bv.w);
            if (which) {
                float rs = rsqrtf(fmaxf((float)g_sdeg[gr], 1.0f));
                __half2 h01 = __floats2half2_rn(o.x * rs, o.y * rs);
                __half2 h23 = __floats2half2_rn(o.z * rs, o.w * rs);
                uint2 pk;
                pk.x = *(unsigned*)&h01; pk.y = *(unsigned*)&h23;
                *(uint2*)&g_conv_h[(long)gr * DD + lane * 4] = pk;
            } else {
                ((float4*)out_h)[(long)gr * 32 + lane] = o;
            }
        }
    }
}

// ---------------------------------------------------------------- CSR pull + fused epilogue
// One warp per receiver node. acc = sum of in-edge conv rows (fp16 gather, fp32 accum);
// h = relu(h1 + acc*rsqrt(rdeg) + gvec) + nodes; also column sums -> g_an.
__global__ __launch_bounds__(256) void k_gather(const float* __restrict__ nodes,
                                                float* __restrict__ out) {
    __shared__ float4 sred[256];
    const int tid  = threadIdx.x;
    const int lane = tid & 31;
    const int wy   = tid >> 5;
    const int r    = blockIdx.x * 8 + wy;      // node id
    float4 sum = make_float4(0.f, 0.f, 0.f, 0.f);

    if (r < NNODES) {
        const int start = g_offs[r];
        const int deg   = g_rdeg[r];
        float4 acc = make_float4(0.f, 0.f, 0.f, 0.f);
        int j = 0;
        for (; j + 1 < deg; j += 2) {          // unroll 2 for MLP
            int s0 = g_csr[start + j];
            int s1 = g_csr[start + j + 1];
            uint2 a0 = *(const uint2*)&g_conv_h[(long)s0 * DD + lane * 4];
            uint2 a1 = *(const uint2*)&g_conv_h[(long)s1 * DD + lane * 4];
            float2 p00 = __half22float2(*(__half2*)&a0.x);
            float2 p01 = __half22float2(*(__half2*)&a0.y);
            float2 p10 = __half22float2(*(__half2*)&a1.x);
            float2 p11 = __half22float2(*(__half2*)&a1.y);
            acc.x += p00.x + p10.x; acc.y += p00.y + p10.y;
            acc.z += p01.x + p11.x; acc.w += p01.y + p11.y;
        }
        if (j < deg) {
            int s0 = g_csr[start + j];
            uint2 a0 = *(const uint2*)&g_conv_h[(long)s0 * DD + lane * 4];
            float2 p00 = __half22float2(*(__half2*)&a0.x);
            float2 p01 = __half22float2(*(__half2*)&a0.y);
            acc.x += p00.x; acc.y += p00.y; acc.z += p01.x; acc.w += p01.y;
        }
        float rs = rsqrtf(fmaxf((float)deg, 1.0f));
        float4 gv = ((const float4*)g_gvec)[lane];
        long off = (long)r * 32 + lane;
        float4 h  = ((float4*)out)[off];
        float4 nd = ((const float4*)nodes)[off];
        float4 o;
        o.x = fmaxf(h.x + acc.x * rs + gv.x, 0.f) + nd.x;
        o.y = fmaxf(h.y + acc.y * rs + gv.y, 0.f) + nd.y;
        o.z = fmaxf(h.z + acc.z * rs + gv.z, 0.f) + nd.z;
        o.w = fmaxf(h.w + acc.w * rs + gv.w, 0.f) + nd.w;
        ((float4*)out)[off] = o;
        sum = o;
    }
    sred[tid] = sum;
    __syncthreads();
    if (wy == 0) {
        float4 s = sred[lane];
        #pragma unroll
        for (int jj = 1; jj < 8; jj++) {
            float4 t = sred[jj * 32 + lane];
            s.x += t.x; s.y += t.y; s.z += t.z; s.w += t.w;
        }
        float* addr = &g_an[lane * 4];
        asm volatile("red.global.add.v4.f32 [%0], {%1,%2,%3,%4};"
                     :: "l"(addr), "f"(s.x), "f"(s.y), "f"(s.z), "f"(s.w)
                     : "memory");
    }
}

// ---------------------------------------------------------------- global update
__global__ void k_global(const float* __restrict__ gl, const float* __restrict__ Wg,
                         const float* __restrict__ bg, float* __restrict__ outg) {
    __shared__ float red[2 * DD];
    int c = blockIdx.x, t = threadIdx.x;
    float x = (t < DD) ? g_an[t] : gl[t - DD];
    red[t] = x * Wg[t * DD + c];
    __syncthreads();
    if (t < 128) red[t] += red[t + 128];
    __syncthreads();
    if (t < 64) red[t] += red[t + 64];
    __syncthreads();
    if (t < 32) {
        float v = red[t] + red[t + 32];
        #pragma unroll
        for (int o = 16; o > 0; o >>= 1) v += __shfl_down_sync(0xffffffff, v, o);
        if (t == 0) outg[c] = gl[c] + fmaxf(v + bg[c], 0.f);
    }
}

// ---------------------------------------------------------------- launch
extern "C" void kernel_launch(void* const* d_in, const int* in_sizes, int n_in,
                              void* d_out, int out_size) {
    const float* nodes    = (const float*)d_in[0];
    const float* globals_ = (const float*)d_in[1];
    const int*   senders   = (const int*)d_in[2];
    const int*   receivers = (const int*)d_in[3];
    const float* W1w = (const float*)d_in[4];
    const float* W1b = (const float*)d_in[5];
    const float* W2w = (const float*)d_in[6];
    const float* W2b = (const float*)d_in[7];
    const float* W3w = (const float*)d_in[8];
    const float* W3b = (const float*)d_in[9];
    const float* Wgw = (const float*)d_in[10];
    const float* Wgb = (const float*)d_in[11];
    float* out = (float*)d_out;

    const int smem = 64 * DD * 8;    // 65536 B
    cudaFuncSetAttribute(k_gemm, cudaFuncAttributeMaxDynamicSharedMemorySize, smem);

    k_zero<<<(NNODES + 255) / 256, 256>>>(globals_, W3w, W3b);
    k_deg<<<(NEDGES + 255) / 256, 256>>>(senders, receivers);
    k_scanA<<<SCAN_BLK, 1024>>>();
    k_scanB<<<1, 128>>>();
    k_scanC<<<(NNODES + 255) / 256, 256>>>();
    k_scatter<<<(NEDGES + 255) / 256, 256>>>(senders, receivers);
    dim3 gg((NNODES + 63) / 64, 2);
    k_gemm<<<gg, 256, smem>>>(nodes, W1w, W1b, W2w, W2b, out);
    k_gather<<<(NNODES + 7) / 8, 256>>>(nodes, out);
    k_global<<<DD, 2 * DD>>>(globals_, Wgw, Wgb, out + (long)NNODES * DD);
}

// round 8
// speedup vs baseline: 1.4974x; 1.0534x over previous
#include <cuda_runtime.h>
#include <cuda_fp16.h>
#include <math.h>
#include <stdint.h>

#define NNODES 100000
#define NEDGES 640000
#define DD 128
#define SCAN_BLK 98            // ceil(100000/1024)

// Scratch (__device__ globals: allocation-free rule)
__device__ __half g_conv_h[NNODES * DD];   // conv = nodes@W2 + b2 (UNSCALED), fp16
__device__ int    g_sdeg[NNODES];
__device__ int    g_rdeg[NNODES];
__device__ int    g_scan[NNODES];
__device__ int    g_bsum[SCAN_BLK];
__device__ int    g_boff[SCAN_BLK];
__device__ int    g_offs[NNODES];          // CSR row starts (in-edges per receiver)
__device__ int    g_cur[NNODES];
__device__ int    g_csr[NEDGES];           // sender ids grouped by receiver
__device__ float  g_rss[NNODES];           // rsqrt(max(sdeg,1))
__device__ float  g_gvec[DD];
__device__ float  g_an[DD];

// packed fp32x2 FMA
#define FMA_F32X2(acc, a, b) \
    asm("fma.rn.f32x2 %0, %1, %2, %0;" : "+l"(acc) : "l"(a), "l"(b))

__device__ __forceinline__ unsigned long long dup2(float f) {
    unsigned u = __float_as_uint(f);
    return (unsigned long long)u | ((unsigned long long)u << 32);
}
__device__ __forceinline__ float2 unpk(unsigned long long v) {
    return make_float2(__uint_as_float((unsigned)v), __uint_as_float((unsigned)(v >> 32)));
}

// ---------------------------------------------------------------- zero + gvec fused
__global__ void k_zero(const float* __restrict__ gl, const float* __restrict__ W3,
                       const float* __restrict__ b3) {
    int i = blockIdx.x * blockDim.x + threadIdx.x;
    if (i < NNODES) { g_sdeg[i] = 0; g_rdeg[i] = 0; }
    if (i < DD) g_an[i] = 0.f;
    if (blockIdx.x < DD) {
        __shared__ float red[DD];
        int c = blockIdx.x, t = threadIdx.x;
        if (t < DD) red[t] = gl[t] * W3[t * DD + c];
        __syncthreads();
        if (t < 64) red[t] += red[t + 64];
        __syncthreads();
        if (t < 32) {
            float v = red[t] + red[t + 32];
            #pragma unroll
            for (int o = 16; o > 0; o >>= 1) v += __shfl_down_sync(0xffffffff, v, o);
            if (t == 0) g_gvec[c] = v + b3[c];
        }
    }
}

// ---------------------------------------------------------------- degrees
__global__ void k_deg(const int* __restrict__ snd, const int* __restrict__ rcv) {
    int e = blockIdx.x * blockDim.x + threadIdx.x;
    if (e < NEDGES) {
        atomicAdd(&g_sdeg[snd[e]], 1);
        atomicAdd(&g_rdeg[rcv[e]], 1);
    }
}

// ---------------------------------------------------------------- prefix scan
__global__ __launch_bounds__(1024) void k_scanA() {
    __shared__ int sh[1024];
    int i = blockIdx.x * 1024 + threadIdx.x;
    int v = (i < NNODES) ? g_rdeg[i] : 0;
    sh[threadIdx.x] = v;
    __syncthreads();
    #pragma unroll
    for (int o = 1; o < 1024; o <<= 1) {
        int t = (threadIdx.x >= o) ? sh[threadIdx.x - o] : 0;
        __syncthreads();
        sh[threadIdx.x] += t;
        __syncthreads();
    }
    if (i < NNODES) g_scan[i] = sh[threadIdx.x];
    if (threadIdx.x == 1023) g_bsum[blockIdx.x] = sh[1023];
}
__global__ void k_scanB() {
    __shared__ int sh[128];
    int t = threadIdx.x;
    int v = (t < SCAN_BLK) ? g_bsum[t] : 0;
    sh[t] = v;
    __syncthreads();
    #pragma unroll
    for (int o = 1; o < 128; o <<= 1) {
        int u = (t >= o) ? sh[t - o] : 0;
        __syncthreads();
        sh[t] += u;
        __syncthreads();
    }
    if (t < SCAN_BLK) g_boff[t] = sh[t] - v;
}
__global__ void k_scanC() {
    int i = blockIdx.x * blockDim.x + threadIdx.x;
    if (i < NNODES) {
        int off = g_scan[i] - g_rdeg[i] + g_boff[i >> 10];
        g_offs[i] = off;
        g_cur[i]  = off;
        g_rss[i]  = rsqrtf(fmaxf((float)g_sdeg[i], 1.0f));
    }
}

// ---------------------------------------------------------------- CSR scatter
__global__ void k_scatter(const int* __restrict__ snd, const int* __restrict__ rcv) {
    int e = blockIdx.x * blockDim.x + threadIdx.x;
    if (e < NEDGES) {
        int r = rcv[e];
        int pos = atomicAdd(&g_cur[r], 1);
        g_csr[pos] = snd[e];
    }
}

// ---------------------------------------------------------------- f32x2 GEMM (no external deps)
extern __shared__ unsigned long long As2[];   // 64KB
__global__ __launch_bounds__(256) void k_gemm(
    const float* __restrict__ A,
    const float* __restrict__ W1, const float* __restrict__ b1,
    const float* __restrict__ W2, const float* __restrict__ b2,
    float* __restrict__ out_h)
{
    const int which = blockIdx.y;
    const float* W    = which ? W2 : W1;
    const float* bias = which ? b2 : b1;
    const int rowBase = blockIdx.x * 64;
    const int tid = threadIdx.x;
    const int maxr = NNODES - rowBase;

    const float4* A4 = (const float4*)(A + (long)rowBase * DD);
    #pragma unroll
    for (int i = 0; i < 8; i++) {
        int idx4 = tid + i * 256;
        int row = idx4 >> 5, col4 = (idx4 & 31) << 2;
        float4 v = make_float4(0.f, 0.f, 0.f, 0.f);
        if (row < maxr) v = A4[idx4];
        unsigned long long* d = &As2[row * DD + col4];
        d[0] = dup2(v.x); d[1] = dup2(v.y); d[2] = dup2(v.z); d[3] = dup2(v.w);
    }
    __syncthreads();

    const int lane = tid & 31;
    const int ty   = tid >> 5;
    unsigned long long acc[8][2];
    #pragma unroll
    for (int i = 0; i < 8; i++) { acc[i][0] = 0ull; acc[i][1] = 0ull; }

    const unsigned long long* Asrow = &As2[ty * 8 * DD];
    #pragma unroll 8
    for (int k = 0; k < DD; k++) {
        ulonglong2 wp = *(const ulonglong2*)(W + (long)k * DD + lane * 4);
        #pragma unroll
        for (int i = 0; i < 8; i++) {
            unsigned long long ap = Asrow[i * DD + k];
            FMA_F32X2(acc[i][0], ap, wp.x);
            FMA_F32X2(acc[i][1], ap, wp.y);
        }
    }

    float4 bv = ((const float4*)bias)[lane];
    #pragma unroll
    for (int i = 0; i < 8; i++) {
        int r = ty * 8 + i;
        if (r < maxr) {
            int gr = rowBase + r;
            float2 p0 = unpk(acc[i][0]);
            float2 p1 = unpk(acc[i][1]);
            float4 o = make_float4(p0.x + bv.x, p0.y + bv.y, p1.x + bv.z, p1.y + bv.w);
            if (which) {
                __half2 h01 = __floats2half2_rn(o.x, o.y);     // UNSCALED conv
                __half2 h23 = __floats2half2_rn(o.z, o.w);
                uint2 pk;
                pk.x = *(unsigned*)&h01; pk.y = *(unsigned*)&h23;
                *(uint2*)&g_conv_h[(long)gr * DD + lane * 4] = pk;
            } else {
                ((float4*)out_h)[(long)gr * 32 + lane] = o;
            }
        }
    }
}

// ---------------------------------------------------------------- CSR pull + fused epilogue
__global__ __launch_bounds__(256) void k_gather(const float* __restrict__ nodes,
                                                float* __restrict__ out) {
    __shared__ float4 sred[256];
    const int tid  = threadIdx.x;
    const int lane = tid & 31;
    const int wy   = tid >> 5;
    const int r    = blockIdx.x * 8 + wy;
    float4 sum = make_float4(0.f, 0.f, 0.f, 0.f);

    if (r < NNODES) {
        const int start = g_offs[r];
        const int deg   = g_rdeg[r];
        float4 acc = make_float4(0.f, 0.f, 0.f, 0.f);
        int j = 0;
        for (; j + 1 < deg; j += 2) {
            int s0 = g_csr[start + j];
            int s1 = g_csr[start + j + 1];
            float w0 = g_rss[s0];
            float w1 = g_rss[s1];
            uint2 a0 = *(const uint2*)&g_conv_h[(long)s0 * DD + lane * 4];
            uint2 a1 = *(const uint2*)&g_conv_h[(long)s1 * DD + lane * 4];
            float2 p00 = __half22float2(*(__half2*)&a0.x);
            float2 p01 = __half22float2(*(__half2*)&a0.y);
            float2 p10 = __half22float2(*(__half2*)&a1.x);
            float2 p11 = __half22float2(*(__half2*)&a1.y);
            acc.x = fmaf(p00.x, w0, fmaf(p10.x, w1, acc.x));
            acc.y = fmaf(p00.y, w0, fmaf(p10.y, w1, acc.y));
            acc.z = fmaf(p01.x, w0, fmaf(p11.x, w1, acc.z));
            acc.w = fmaf(p01.y, w0, fmaf(p11.y, w1, acc.w));
        }
        if (j < deg) {
            int s0 = g_csr[start + j];
            float w0 = g_rss[s0];
            uint2 a0 = *(const uint2*)&g_conv_h[(long)s0 * DD + lane * 4];
            float2 p00 = __half22float2(*(__half2*)&a0.x);
            float2 p01 = __half22float2(*(__half2*)&a0.y);
            acc.x = fmaf(p00.x, w0, acc.x);
            acc.y = fmaf(p00.y, w0, acc.y);
            acc.z = fmaf(p01.x, w0, acc.z);
            acc.w = fmaf(p01.y, w0, acc.w);
        }
        float rs = rsqrtf(fmaxf((float)deg, 1.0f));
        float4 gv = ((const float4*)g_gvec)[lane];
        long off = (long)r * 32 + lane;
        float4 h  = ((float4*)out)[off];
        float4 nd = ((const float4*)nodes)[off];
        float4 o;
        o.x = fmaxf(h.x + acc.x * rs + gv.x, 0.f) + nd.x;
        o.y = fmaxf(h.y + acc.y * rs + gv.y, 0.f) + nd.y;
        o.z = fmaxf(h.z + acc.z * rs + gv.z, 0.f) + nd.z;
        o.w = fmaxf(h.w + acc.w * rs + gv.w, 0.f) + nd.w;
        ((float4*)out)[off] = o;
        sum = o;
    }
    sred[tid] = sum;
    __syncthreads();
    if (wy == 0) {
        float4 s = sred[lane];
        #pragma unroll
        for (int jj = 1; jj < 8; jj++) {
            float4 t = sred[jj * 32 + lane];
            s.x += t.x; s.y += t.y; s.z += t.z; s.w += t.w;
        }
        float* addr = &g_an[lane * 4];
        asm volatile("red.global.add.v4.f32 [%0], {%1,%2,%3,%4};"
                     :: "l"(addr), "f"(s.x), "f"(s.y), "f"(s.z), "f"(s.w)
                     : "memory");
    }
}

// ---------------------------------------------------------------- global update
__global__ void k_global(const float* __restrict__ gl, const float* __restrict__ Wg,
                         const float* __restrict__ bg, float* __restrict__ outg) {
    __shared__ float red[2 * DD];
    int c = blockIdx.x, t = threadIdx.x;
    float x = (t < DD) ? g_an[t] : gl[t - DD];
    red[t] = x * Wg[t * DD + c];
    __syncthreads();
    if (t < 128) red[t] += red[t + 128];
    __syncthreads();
    if (t < 64) red[t] += red[t + 64];
    __syncthreads();
    if (t < 32) {
        float v = red[t] + red[t + 32];
        #pragma unroll
        for (int o = 16; o > 0; o >>= 1) v += __shfl_down_sync(0xffffffff, v, o);
        if (t == 0) outg[c] = gl[c] + fmaxf(v + bg[c], 0.f);
    }
}

// ---------------------------------------------------------------- launch (forked graph)
// Stream/events created ONCE (first call = uncaptured correctness run).
// Every call issues the identical, deterministic launch sequence.
extern "C" void kernel_launch(void* const* d_in, const int* in_sizes, int n_in,
                              void* d_out, int out_size) {
    const float* nodes    = (const float*)d_in[0];
    const float* globals_ = (const float*)d_in[1];
    const int*   senders   = (const int*)d_in[2];
    const int*   receivers = (const int*)d_in[3];
    const float* W1w = (const float*)d_in[4];
    const float* W1b = (const float*)d_in[5];
    const float* W2w = (const float*)d_in[6];
    const float* W2b = (const float*)d_in[7];
    const float* W3w = (const float*)d_in[8];
    const float* W3b = (const float*)d_in[9];
    const float* Wgw = (const float*)d_in[10];
    const float* Wgb = (const float*)d_in[11];
    float* out = (float*)d_out;

    static cudaStream_t s1 = nullptr;
    static cudaEvent_t evRoot = nullptr, evSide = nullptr;
    if (s1 == nullptr) {
        cudaFuncSetAttribute(k_gemm, cudaFuncAttributeMaxDynamicSharedMemorySize, 64 * DD * 8);
        cudaStreamCreateWithFlags(&s1, cudaStreamNonBlocking);
        cudaEventCreateWithFlags(&evRoot, cudaEventDisableTiming);
        cudaEventCreateWithFlags(&evSide, cudaEventDisableTiming);
    }

    // fork: side stream joins the (possibly capturing) main stream via event
    cudaEventRecord(evRoot, 0);
    cudaStreamWaitEvent(s1, evRoot, 0);

    // side chain: zero/gvec -> degrees -> scan -> CSR scatter
    k_zero<<<(NNODES + 255) / 256, 256, 0, s1>>>(globals_, W3w, W3b);
    k_deg<<<(NEDGES + 255) / 256, 256, 0, s1>>>(senders, receivers);
    k_scanA<<<SCAN_BLK, 1024, 0, s1>>>();
    k_scanB<<<1, 128, 0, s1>>>();
    k_scanC<<<(NNODES + 255) / 256, 256, 0, s1>>>();
    k_scatter<<<(NEDGES + 255) / 256, 256, 0, s1>>>(senders, receivers);
    cudaEventRecord(evSide, s1);

    // main: dual GEMM (independent of side chain)
    dim3 gg((NNODES + 63) / 64, 2);
    k_gemm<<<gg, 256, 64 * DD * 8>>>(nodes, W1w, W1b, W2w, W2b, out);

    // join, then pull-aggregate + fused epilogue, then global update
    cudaStreamWaitEvent(0, evSide, 0);
    k_gather<<<(NNODES + 7) / 8, 256>>>(nodes, out);
    k_global<<<DD, 2 * DD>>>(globals_, Wgw, Wgb, out + (long)NNODES * DD);
}